// round 16
// baseline (speedup 1.0000x reference)
#include <cuda_runtime.h>
#include <cuda_bf16.h>
#include <cstdint>
#include <math_constants.h>

#define T_STEPS 1024
#define DIM     300
#define HD1     1024
#define HD2     512
#define VGLOB   50000
#define VSENS   25000
#define NR      128          // rnn CTAs: 1024 = 128*8, 512 = 128*4

#define TILES_G 391
#define TILES_S 196
#define TPB     (TILES_G + TILES_S)   // 587 tiles per m-block
#define NSUB    12                    // 8 G-chunks + 4 S-chunks, 6250 cols each
#define ITEMS   (TPB + 1 + NSUB)      // 600 queue items per m-block
#define NQ      (8 * ITEMS)           // 4800
#define PSTR_G  392
#define PSTR_S  200

// dynamic smem layout
#define GRP_BYTES 43520   // sA 20480 + sB 20480 + bias/lse 512 + sM 1024 + sS 1024
#define DYN_BYTES (256 + 2 * GRP_BYTES)

// ------------------------- device scratch -------------------------
__device__ __align__(16) float g_U1[T_STEPS * HD1];
__device__ __align__(16) float g_h1rep[8][4][HD1];   // [copy][parity r&3][HD1]
__device__ __align__(16) float g_h2rep[8][2][HD2];   // [copy][parity][HD2]
__device__ __align__(128) unsigned g_cnt1[8 * 32];
__device__ __align__(128) unsigned g_cnt2[8 * 32];
__device__ __align__(128) unsigned g_tileCtr[32];
__device__ __align__(128) unsigned g_done[8 * 32];     // per-m-block tile completion
__device__ __align__(128) unsigned g_lseDone[8 * 32];  // per-m-block lse completion
__device__ float g_pmaxG[T_STEPS * PSTR_G];
__device__ float g_psumG[T_STEPS * PSTR_G];
__device__ float g_pmaxS[T_STEPS * PSTR_S];
__device__ float g_psumS[T_STEPS * PSTR_S];
__device__ float g_lseG[T_STEPS];
__device__ float g_lseS[T_STEPS];
// bf16 operands for the logits GEMM
__device__ __align__(16) uint16_t g_h2sb[T_STEPS * HD2];
__device__ __align__(16) uint16_t g_Wgb[(size_t)VGLOB * HD2];
__device__ __align__(16) uint16_t g_Wsb[(size_t)VSENS * HD2];

// ------------------------- helpers -------------------------
__device__ __forceinline__ void red_release(unsigned* p, unsigned v) {
    asm volatile("red.release.gpu.global.add.u32 [%0], %1;" :: "l"(p), "r"(v) : "memory");
}
__device__ __forceinline__ unsigned ld_acquire(const unsigned* p) {
    unsigned v;
    asm volatile("ld.acquire.gpu.global.u32 %0, [%1];" : "=r"(v) : "l"(p) : "memory");
    return v;
}
__device__ __forceinline__ void stcg4(float* p, float4 v) {
    asm volatile("st.global.cg.v4.f32 [%0], {%1,%2,%3,%4};"
                 :: "l"(p), "f"(v.x), "f"(v.y), "f"(v.z), "f"(v.w) : "memory");
}
__device__ __forceinline__ void bar_sync(int id) {
    asm volatile("bar.sync %0, 256;" :: "r"(id) : "memory");
}

__device__ __forceinline__ void mma_bf16(float c[4], const uint32_t a[4], const uint32_t b[2]) {
    asm volatile(
        "mma.sync.aligned.m16n8k16.row.col.f32.bf16.bf16.f32 "
        "{%0,%1,%2,%3}, {%4,%5,%6,%7}, {%8,%9}, {%0,%1,%2,%3};"
        : "+f"(c[0]), "+f"(c[1]), "+f"(c[2]), "+f"(c[3])
        : "r"(a[0]), "r"(a[1]), "r"(a[2]), "r"(a[3]), "r"(b[0]), "r"(b[1]));
}

__device__ __forceinline__ void cp_async16(void* dst_smem, const void* src, int src_bytes) {
    uint32_t d = (uint32_t)__cvta_generic_to_shared(dst_smem);
    asm volatile("cp.async.cg.shared.global [%0], [%1], 16, %2;"
                 :: "r"(d), "l"(src), "r"(src_bytes));
}
__device__ __forceinline__ void cp_commit() { asm volatile("cp.async.commit_group;"); }
template <int N>
__device__ __forceinline__ void cp_wait() { asm volatile("cp.async.wait_group %0;" :: "n"(N)); }

__device__ __forceinline__ void lse_merge(float& M, float& S, float m, float s) {
    float nm = fmaxf(M, m);
    if (nm == -CUDART_INF_F) { M = nm; S = 0.f; return; }
    S = S * __expf(M - nm) + s * __expf(m - nm);
    M = nm;
}

__device__ __forceinline__ uint32_t pack_bf16(float a, float b) {
    __nv_bfloat16 ba = __float2bfloat16(a), bb = __float2bfloat16(b);
    return (uint32_t)reinterpret_cast<unsigned short&>(ba) |
           ((uint32_t)reinterpret_cast<unsigned short&>(bb) << 16);
}

// ------------------------- init -------------------------
__global__ void init_kernel() {
    int tid = threadIdx.x + blockIdx.x * blockDim.x;
    int stride = gridDim.x * blockDim.x;
    if (tid < 8 * 32) { g_cnt1[tid] = 0u; g_cnt2[tid] = 0u; g_done[tid] = 0u; g_lseDone[tid] = 0u; }
    if (tid < 32) g_tileCtr[tid] = 0u;
    for (int i = tid; i < 8 * 4 * HD1; i += stride) ((float*)g_h1rep)[i] = 0.f;
    for (int i = tid; i < 8 * 2 * HD2; i += stride) ((float*)g_h2rep)[i] = 0.f;
}

// ------------------------- fp32 -> bf16 weight conversion -------------------------
__global__ void convert_kernel(const float* __restrict__ src, uint16_t* __restrict__ dst, int n4) {
    int i = blockIdx.x * blockDim.x + threadIdx.x;
    int stride = gridDim.x * blockDim.x;
    uint32_t* d32 = (uint32_t*)dst;
    const float4* s4 = (const float4*)src;
    for (; i < n4; i += stride) {
        float4 v = s4[i];
        d32[2 * i]     = pack_bf16(v.x, v.y);
        d32[2 * i + 1] = pack_bf16(v.z, v.w);
    }
}

// ------------------------- U1 = E @ W1e^T + b1 -------------------------
__global__ void __launch_bounds__(256) u1_kernel(const float* __restrict__ X,
                                                 const float* __restrict__ W1,
                                                 const float* __restrict__ b1,
                                                 const int* __restrict__ idx) {
    __shared__ float sA[20][64];
    __shared__ float sB[20][64];
    __shared__ int sidx[64];
    int tid = threadIdx.x;
    int t0 = blockIdx.y * 64, i0 = blockIdx.x * 64;
    if (tid < 64) sidx[tid] = idx[t0 + tid];
    __syncthreads();
    float acc[4][4];
#pragma unroll
    for (int a = 0; a < 4; ++a)
#pragma unroll
        for (int b = 0; b < 4; ++b) acc[a][b] = 0.f;
    int tx = tid & 15, ty = tid >> 4;
    for (int kc = 0; kc < 15; ++kc) {
        int k0 = kc * 20;
        for (int i = tid; i < 1280; i += 256) {
            int k = i >> 6, m = i & 63;
            sA[k][m] = X[(long)sidx[m] * DIM + k0 + k];
            sB[k][m] = W1[(long)(i0 + m) * (DIM + HD1) + k0 + k];
        }
        __syncthreads();
#pragma unroll
        for (int k = 0; k < 20; ++k) {
            float a[4], b[4];
#pragma unroll
            for (int e = 0; e < 4; ++e) { a[e] = sA[k][ty * 4 + e]; b[e] = sB[k][tx * 4 + e]; }
#pragma unroll
            for (int ii = 0; ii < 4; ++ii)
#pragma unroll
                for (int jj = 0; jj < 4; ++jj) acc[ii][jj] += a[ii] * b[jj];
        }
        __syncthreads();
    }
#pragma unroll
    for (int ii = 0; ii < 4; ++ii)
#pragma unroll
        for (int jj = 0; jj < 4; ++jj) {
            int t = t0 + ty * 4 + ii, n = i0 + tx * 4 + jj;
            g_U1[t * HD1 + n] = acc[ii][jj] + b1[n];
        }
}

// ------------------------- unified work item processor (256 threads) ------------------
// Queue items per m-block: [0,TPB) GEMM tiles -> release g_done;
// TPB = LSE item (gates g_done == TPB*256, writes g_lse*, releases g_lseDone);
// (TPB, TPB+NSUB] = sub-chunks (gate g_lseDone == 256; in-place logp subtract).
__device__ __noinline__ void tile_worker(char* grp, int ltid, int barid, int cpy,
                                         const float* bg, const float* bs,
                                         float* outG, float* outS, int* sTT) {
    uint16_t* sA = (uint16_t*)grp;                   // [2][128*40]
    uint16_t* sB = (uint16_t*)(grp + 20480);         // [2][128*40]
    float* sBias = (float*)(grp + 40960);            // [128] (bias / lse cache)
    float* sM    = (float*)(grp + 41472);            // [128*2]
    float* sS_   = (float*)(grp + 42496);            // [128*2]
    int lane = ltid & 31;
    int lwarp = ltid >> 5;
    int wm = lwarp & 3, wn = lwarp >> 2;

    for (;;) {
        if (ltid == 0) *sTT = (int)atomicAdd(&g_tileCtr[0], 1u);
        bar_sync(barid);
        int it = *sTT;
        bar_sync(barid);
        if (it >= NQ) break;

        int blk = it / ITEMS, rem = it % ITEMS;
        int m0 = blk * 128;

        if (rem < TPB) {
            // =============== GEMM tile ===============
            bool isS = rem >= TILES_G;
            int ntile = isS ? rem - TILES_G : rem;
            const uint16_t* Wb = isS ? g_Wsb : g_Wgb;
            const float* bias = isS ? bs : bg;
            float* out = isS ? outS : outG;
            float* pmax = isS ? g_pmaxS : g_pmaxG;
            float* psum = isS ? g_psumS : g_psumG;
            const int V = isS ? VSENS : VGLOB;
            const int pstr = isS ? PSTR_S : PSTR_G;
            int n0 = ntile * 128;

            if (ltid == 0) {   // gate: h2s rows <= m0+127 published
                unsigned tgt = (unsigned)(m0 + 128) * NR;
                while (ld_acquire(&g_cnt2[cpy * 32]) < tgt) {}
            }
            if (ltid < 128) {
                int v = n0 + ltid;
                sBias[ltid] = (v < V) ? bias[v] : 0.f;
            }
            bar_sync(barid);

            float acc[2][8][4];
#pragma unroll
            for (int mt = 0; mt < 2; ++mt)
#pragma unroll
                for (int nt = 0; nt < 8; ++nt)
#pragma unroll
                    for (int e = 0; e < 4; ++e) acc[mt][nt][e] = 0.f;

            auto issue = [&](int kc, int s) {
                int k0 = kc * 32;
#pragma unroll
                for (int p = 0; p < 2; ++p) {
                    int f = ltid + p * 256;
                    int row = f >> 2, seg = f & 3;
                    cp_async16(&sA[s * 5120 + row * 40 + seg * 8],
                               &g_h2sb[(long)(m0 + row) * HD2 + k0 + seg * 8], 16);
                    int vr = n0 + row;
                    int srow = vr < V ? vr : 0;
                    cp_async16(&sB[s * 5120 + row * 40 + seg * 8],
                               &Wb[(long)srow * HD2 + k0 + seg * 8], vr < V ? 16 : 0);
                }
                cp_commit();
            };

            issue(0, 0);
            for (int kc = 0; kc < 16; ++kc) {
                if (kc + 1 < 16) { issue(kc + 1, (kc + 1) & 1); cp_wait<1>(); }
                else             { cp_wait<0>(); }
                bar_sync(barid);
                const uint16_t* pA = sA + (kc & 1) * 5120;
                const uint16_t* pB = sB + (kc & 1) * 5120;
#pragma unroll
                for (int ks = 0; ks < 2; ++ks) {
                    int kk = ks * 16;
                    uint32_t a[2][4], b[8][2];
                    int ar = wm * 32 + (lane >> 2);
                    int ac = kk + (lane & 3) * 2;
#pragma unroll
                    for (int mt = 0; mt < 2; ++mt) {
                        const uint16_t* base = &pA[(ar + mt * 16) * 40 + ac];
                        a[mt][0] = *(const uint32_t*)(base);
                        a[mt][1] = *(const uint32_t*)(base + 8 * 40);
                        a[mt][2] = *(const uint32_t*)(base + 8);
                        a[mt][3] = *(const uint32_t*)(base + 8 * 40 + 8);
                    }
                    int br = wn * 64 + (lane >> 2);
#pragma unroll
                    for (int nt = 0; nt < 8; ++nt) {
                        const uint16_t* base = &pB[(br + nt * 8) * 40 + ac];
                        b[nt][0] = *(const uint32_t*)(base);
                        b[nt][1] = *(const uint32_t*)(base + 8);
                    }
#pragma unroll
                    for (int mt = 0; mt < 2; ++mt)
#pragma unroll
                        for (int nt = 0; nt < 8; ++nt) mma_bf16(acc[mt][nt], a[mt], b[nt]);
                }
                bar_sync(barid);
            }

            int rbase = wm * 32 + (lane >> 2);
            int cbase = wn * 64 + (lane & 3) * 2;
#pragma unroll
            for (int mt = 0; mt < 2; ++mt)
#pragma unroll
                for (int h = 0; h < 2; ++h) {
                    int rr = rbase + mt * 16 + h * 8;
                    long t = m0 + rr;
                    float xs[16];
                    float M = -CUDART_INF_F;
#pragma unroll
                    for (int nt = 0; nt < 8; ++nt)
#pragma unroll
                        for (int e = 0; e < 2; ++e) {
                            int cc = cbase + nt * 8 + e;
                            int v = n0 + cc;
                            float x = -CUDART_INF_F;
                            if (v < V) {
                                x = acc[mt][nt][h * 2 + e] + sBias[cc];
                                out[t * V + v] = x;
                                M = fmaxf(M, x);
                            }
                            xs[nt * 2 + e] = x;
                        }
                    float S = 0.f;
#pragma unroll
                    for (int i = 0; i < 16; ++i)
                        if (xs[i] != -CUDART_INF_F) S += __expf(xs[i] - M);
#pragma unroll
                    for (int o = 1; o <= 2; o <<= 1) {
                        float m2 = __shfl_xor_sync(~0u, M, o);
                        float s2 = __shfl_xor_sync(~0u, S, o);
                        lse_merge(M, S, m2, s2);
                    }
                    if ((lane & 3) == 0) { sM[rr * 2 + wn] = M; sS_[rr * 2 + wn] = S; }
                }
            bar_sync(barid);
            if (ltid < 128) {
                float M = sM[ltid * 2], S = sS_[ltid * 2];
                lse_merge(M, S, sM[ltid * 2 + 1], sS_[ltid * 2 + 1]);
                long t = m0 + ltid;
                pmax[t * pstr + ntile] = M;
                psum[t * pstr + ntile] = S;
            }
            // EVERY thread releases its own stores for this m-block
            red_release(&g_done[blk * 32], 1u);
        } else if (rem == TPB) {
            // =============== LSE item (once per m-block) ===============
            if (ltid == 0) {
                while (ld_acquire(&g_done[blk * 32]) < (unsigned)(TPB * 256)) {}
            }
            bar_sync(barid);
            int row = ltid >> 1, half = ltid & 1;
            int t = m0 + row;
            {
                float M = -CUDART_INF_F, S = 0.f;
                for (int i = half; i < TILES_G; i += 2)
                    lse_merge(M, S, g_pmaxG[(long)t * PSTR_G + i], g_psumG[(long)t * PSTR_G + i]);
                float m2 = __shfl_xor_sync(~0u, M, 1);
                float s2 = __shfl_xor_sync(~0u, S, 1);
                lse_merge(M, S, m2, s2);
                if (half == 0) g_lseG[t] = M + logf(S);
            }
            {
                float M = -CUDART_INF_F, S = 0.f;
                for (int i = half; i < TILES_S; i += 2)
                    lse_merge(M, S, g_pmaxS[(long)t * PSTR_S + i], g_psumS[(long)t * PSTR_S + i]);
                float m2 = __shfl_xor_sync(~0u, M, 1);
                float s2 = __shfl_xor_sync(~0u, S, 1);
                lse_merge(M, S, m2, s2);
                if (half == 0) g_lseS[t] = M + logf(S);
            }
            red_release(&g_lseDone[blk * 32], 1u);
        } else {
            // =============== sub-chunk: logp = logit - lse ===============
            int sc = rem - TPB - 1;            // 0..11
            bool isS = sc >= 8;
            float* out = isS ? outS : outG;
            const float* lse = isS ? g_lseS : g_lseG;
            const int V = isS ? VSENS : VGLOB;
            int col0 = (isS ? sc - 8 : sc) * 6250;

            if (ltid == 0) {
                while (ld_acquire(&g_lseDone[blk * 32]) < 256u) {}
            }
            bar_sync(barid);
            if (ltid < 128) sBias[ltid] = lse[m0 + ltid];   // lse cache
            bar_sync(barid);

            // 128 rows x 6250 cols, float2 (3125 per row)
            for (int i = ltid; i < 128 * 3125; i += 256) {
                int row = i / 3125, c2 = i % 3125;
                float l = sBias[row];
                float2* p = (float2*)(out + (size_t)(m0 + row) * V + col0) + c2;
                float2 v = *p;
                v.x -= l; v.y -= l;
                *p = v;
            }
            bar_sync(barid);
        }
    }
}

// ------------------------- fused RNN + logits + softmax kernel (512 threads) ----------
// Warps 0-3: h1 chain (bar 1). Warps 4-7: h2 chain (bar 2). Warps 8-15: worker
// group A (bar 3) from start. After RNN retires, warps 0-7 = worker group B (bar 4).
__global__ void __launch_bounds__(512, 1) fused_kernel(const float* __restrict__ W1,
                                                       const float* __restrict__ W2,
                                                       const float* __restrict__ b2,
                                                       const float* __restrict__ bg,
                                                       const float* __restrict__ bs,
                                                       float* __restrict__ outG,
                                                       float* __restrict__ outS) {
    extern __shared__ __align__(16) char dyn[];
    float* sP1 = (float*)dyn;             // 32 floats
    float* sP2 = (float*)(dyn + 128);     // 16 floats
    int* sTT   = (int*)(dyn + 192);       // [2]
    char* grpA = dyn + 256;
    char* grpB = grpA + GRP_BYTES;

    int tid = threadIdx.x, c = blockIdx.x;
    int lane = tid & 31;
    int cpy = c & 7;

    if (tid < 128) {
        // =================== h1 group (warps 0-3) ===================
        int w = tid >> 5;
        float w1r[8][8];   // [jj][q]
#pragma unroll
        for (int q = 0; q < 8; ++q) {
            const float* p = W1 + (long)(c * 8 + q) * (DIM + HD1) + DIM;
#pragma unroll
            for (int jj = 0; jj < 8; ++jj)
                w1r[jj][q] = p[w * 256 + jj * 32 + lane];
        }

        for (int r = 0; r < T_STEPS; ++r) {
            float u1v = 0.f;
            if (tid < 8) u1v = __ldg(&g_U1[r * HD1 + c * 8 + tid]);
            if (tid == 0) {
                if (r >= 4) {   // WAR gate (usually satisfied), overlapping cnt1 wait
                    unsigned t2 = (unsigned)(r - 3) * NR;
                    while (ld_acquire(&g_cnt2[cpy * 32]) < t2) {}
                }
                if (r > 0) {
                    unsigned t1 = (unsigned)r * NR;
                    while (ld_acquire(&g_cnt1[cpy * 32]) < t1) {}
                }
            }
            asm volatile("bar.sync 1, 128;" ::: "memory");

            const float* h1p = g_h1rep[cpy][(r + 3) & 3];   // h1(r-1)
            float p1[8] = {0, 0, 0, 0, 0, 0, 0, 0};
#pragma unroll
            for (int jj = 0; jj < 8; ++jj) {
                float h = __ldcg(&h1p[w * 256 + jj * 32 + lane]);
#pragma unroll
                for (int q = 0; q < 8; ++q) p1[q] += w1r[jj][q] * h;
            }
#pragma unroll
            for (int q = 0; q < 8; ++q)
#pragma unroll
                for (int o = 16; o; o >>= 1) p1[q] += __shfl_xor_sync(~0u, p1[q], o);
            if (lane == 0) {
#pragma unroll
                for (int q = 0; q < 8; ++q) sP1[q * 4 + w] = p1[q];
            }
            asm volatile("bar.sync 1, 128;" ::: "memory");

            if (w == 0) {
                float s = 0.f;
                if (lane < 8) {
                    float4 ps = *(const float4*)&sP1[lane * 4];
                    s = u1v + ps.x + ps.y + ps.z + ps.w;
                    s = s > 0.f ? s : 0.01f * s;
                }
                float sv[8];
#pragma unroll
                for (int q = 0; q < 8; ++q) sv[q] = __shfl_sync(~0u, s, q);
                if (lane < 8) {
                    float* dst = &g_h1rep[lane][r & 3][c * 8];
                    stcg4(dst,     make_float4(sv[0], sv[1], sv[2], sv[3]));
                    stcg4(dst + 4, make_float4(sv[4], sv[5], sv[6], sv[7]));
                    red_release(&g_cnt1[lane * 32], 1u);
                }
            }
        }
        tile_worker(grpB, tid, 4, cpy, bg, bs, outG, outS, &sTT[1]);
    } else if (tid < 256) {
        // =================== h2 group (warps 4-7) ===================
        int w = (tid >> 5) - 4;
        float w2a[8][4], w2b[4][4];
#pragma unroll
        for (int q = 0; q < 4; ++q) {
            const float* p = W2 + (long)(c * 4 + q) * (HD1 + HD2);
#pragma unroll
            for (int jj = 0; jj < 8; ++jj)
                w2a[jj][q] = p[w * 256 + jj * 32 + lane];
#pragma unroll
            for (int jj = 0; jj < 4; ++jj)
                w2b[jj][q] = p[HD1 + w * 128 + jj * 32 + lane];
        }
        float b2v = 0.f;
        if (tid >= 128 && tid < 132) b2v = b2[c * 4 + (tid - 128)];

        for (int r = 1; r <= T_STEPS; ++r) {
            if (tid == 128) {
                unsigned t1 = (unsigned)r * NR;
                while (ld_acquire(&g_cnt1[cpy * 32]) < t1) {}
                if (r > 1) {
                    unsigned t2 = (unsigned)(r - 1) * NR;
                    while (ld_acquire(&g_cnt2[cpy * 32]) < t2) {}
                }
            }
            asm volatile("bar.sync 2, 128;" ::: "memory");

            const float* h1p = g_h1rep[cpy][(r + 3) & 3];   // h1(r-1)
            const float* h2p = g_h2rep[cpy][r & 1];          // h2(r-2)
            float p2[4] = {0, 0, 0, 0};
#pragma unroll
            for (int jj = 0; jj < 8; ++jj) {
                float h = __ldcg(&h1p[w * 256 + jj * 32 + lane]);
#pragma unroll
                for (int q = 0; q < 4; ++q) p2[q] += w2a[jj][q] * h;
            }
#pragma unroll
            for (int jj = 0; jj < 4; ++jj) {
                float h = __ldcg(&h2p[w * 128 + jj * 32 + lane]);
#pragma unroll
                for (int q = 0; q < 4; ++q) p2[q] += w2b[jj][q] * h;
            }
#pragma unroll
            for (int q = 0; q < 4; ++q)
#pragma unroll
                for (int o = 16; o; o >>= 1) p2[q] += __shfl_xor_sync(~0u, p2[q], o);
            if (lane == 0) {
#pragma unroll
                for (int q = 0; q < 4; ++q) sP2[q * 4 + w] = p2[q];
            }
            asm volatile("bar.sync 2, 128;" ::: "memory");

            if (w == 0) {
                float s = 0.f;
                if (lane < 4) {
                    float4 ps = *(const float4*)&sP2[lane * 4];
                    s = b2v + ps.x + ps.y + ps.z + ps.w;
                    s = s > 0.f ? s : 0.01f * s;
                }
                float sv[4];
#pragma unroll
                for (int q = 0; q < 4; ++q) sv[q] = __shfl_sync(~0u, s, q);
                if (lane < 8) {
                    stcg4(&g_h2rep[lane][(r + 1) & 1][c * 4],
                          make_float4(sv[0], sv[1], sv[2], sv[3]));
                    unsigned long long hv =
                        (unsigned long long)pack_bf16(sv[0], sv[1]) |
                        ((unsigned long long)pack_bf16(sv[2], sv[3]) << 32);
                    *(unsigned long long*)&g_h2sb[(r - 1) * HD2 + c * 4] = hv;
                    red_release(&g_cnt2[lane * 32], 1u);
                }
            }
        }
        tile_worker(grpB, tid, 4, cpy, bg, bs, outG, outS, &sTT[1]);
    } else {
        tile_worker(grpA, tid - 256, 3, cpy, bg, bs, outG, outS, &sTT[0]);
    }
}

// ------------------------- launcher -------------------------
extern "C" void kernel_launch(void* const* d_in, const int* in_sizes, int n_in,
                              void* d_out, int out_size) {
    const float* X  = (const float*)d_in[0];
    const float* W1 = (const float*)d_in[1];
    const float* b1 = (const float*)d_in[2];
    const float* W2 = (const float*)d_in[3];
    const float* b2 = (const float*)d_in[4];
    const float* Wg = (const float*)d_in[5];
    const float* bg = (const float*)d_in[6];
    const float* Ws = (const float*)d_in[7];
    const float* bs = (const float*)d_in[8];
    const int*  idx = (const int*)d_in[9];
    float* outG = (float*)d_out;
    float* outS = outG + (size_t)T_STEPS * VGLOB;

    uint16_t* wgb; cudaGetSymbolAddress((void**)&wgb, g_Wgb);
    uint16_t* wsb; cudaGetSymbolAddress((void**)&wsb, g_Wsb);

    cudaFuncSetAttribute(fused_kernel, cudaFuncAttributeMaxDynamicSharedMemorySize, DYN_BYTES);

    init_kernel<<<64, 256>>>();
    u1_kernel<<<dim3(16, 16), 256>>>(X, W1, b1, idx);
    convert_kernel<<<2048, 256>>>(Wg, wgb, VGLOB * HD2 / 4);
    convert_kernel<<<2048, 256>>>(Ws, wsb, VSENS * HD2 / 4);
    fused_kernel<<<NR, 512, DYN_BYTES>>>(W1, W2, b2, bg, bs, outG, outS);
}

// round 17
// speedup vs baseline: 1.4926x; 1.4926x over previous
#include <cuda_runtime.h>
#include <cuda_bf16.h>
#include <cstdint>
#include <math_constants.h>

#define T_STEPS 1024
#define DIM     300
#define HD1     1024
#define HD2     512
#define VGLOB   50000
#define VSENS   25000
#define NR      128          // rnn CTAs: 1024 = 128*8, 512 = 128*4

#define TILES_G 391
#define TILES_S 196
#define TPB     (TILES_G + TILES_S)   // 587 tiles per m-block
#define NTILES  (8 * TPB)             // 4696
#define PSTR_G  392
#define PSTR_S  200

#define NG4     (VGLOB * HD2 / 4)     // 6,400,000
#define NS4     (VSENS * HD2 / 4)     // 3,200,000

// dynamic smem layout
#define GRP_BYTES 43520   // sA 20480 + sB 20480 + bias 512 + sM 1024 + sS 1024
#define DYN_BYTES (256 + 2 * GRP_BYTES)

// ------------------------- device scratch -------------------------
__device__ __align__(16) float g_U1[T_STEPS * HD1];
__device__ __align__(16) float g_h1rep[8][4][HD1];   // [copy][parity r&3][HD1]
__device__ __align__(16) float g_h2rep[8][2][HD2];   // [copy][parity][HD2]
__device__ __align__(128) unsigned g_cnt1[8 * 32];
__device__ __align__(128) unsigned g_cnt2[8 * 32];
__device__ __align__(128) unsigned g_tileCtr[32];
__device__ float g_pmaxG[T_STEPS * PSTR_G];
__device__ float g_psumG[T_STEPS * PSTR_G];
__device__ float g_pmaxS[T_STEPS * PSTR_S];
__device__ float g_psumS[T_STEPS * PSTR_S];
__device__ float g_lseG[T_STEPS];
__device__ float g_lseS[T_STEPS];
// bf16 operands for the logits GEMM
__device__ __align__(16) uint16_t g_h2sb[T_STEPS * HD2];
__device__ __align__(16) uint16_t g_Wgb[(size_t)VGLOB * HD2];
__device__ __align__(16) uint16_t g_Wsb[(size_t)VSENS * HD2];

// ------------------------- helpers -------------------------
__device__ __forceinline__ void red_release(unsigned* p, unsigned v) {
    asm volatile("red.release.gpu.global.add.u32 [%0], %1;" :: "l"(p), "r"(v) : "memory");
}
__device__ __forceinline__ unsigned ld_acquire(const unsigned* p) {
    unsigned v;
    asm volatile("ld.acquire.gpu.global.u32 %0, [%1];" : "=r"(v) : "l"(p) : "memory");
    return v;
}
__device__ __forceinline__ void stcg4(float* p, float4 v) {
    asm volatile("st.global.cg.v4.f32 [%0], {%1,%2,%3,%4};"
                 :: "l"(p), "f"(v.x), "f"(v.y), "f"(v.z), "f"(v.w) : "memory");
}
__device__ __forceinline__ void bar_sync(int id) {
    asm volatile("bar.sync %0, 256;" :: "r"(id) : "memory");
}

__device__ __forceinline__ void mma_bf16(float c[4], const uint32_t a[4], const uint32_t b[2]) {
    asm volatile(
        "mma.sync.aligned.m16n8k16.row.col.f32.bf16.bf16.f32 "
        "{%0,%1,%2,%3}, {%4,%5,%6,%7}, {%8,%9}, {%0,%1,%2,%3};"
        : "+f"(c[0]), "+f"(c[1]), "+f"(c[2]), "+f"(c[3])
        : "r"(a[0]), "r"(a[1]), "r"(a[2]), "r"(a[3]), "r"(b[0]), "r"(b[1]));
}

__device__ __forceinline__ void cp_async16(void* dst_smem, const void* src, int src_bytes) {
    uint32_t d = (uint32_t)__cvta_generic_to_shared(dst_smem);
    asm volatile("cp.async.cg.shared.global [%0], [%1], 16, %2;"
                 :: "r"(d), "l"(src), "r"(src_bytes));
}
__device__ __forceinline__ void cp_commit() { asm volatile("cp.async.commit_group;"); }
template <int N>
__device__ __forceinline__ void cp_wait() { asm volatile("cp.async.wait_group %0;" :: "n"(N)); }

__device__ __forceinline__ void lse_merge(float& M, float& S, float m, float s) {
    float nm = fmaxf(M, m);
    if (nm == -CUDART_INF_F) { M = nm; S = 0.f; return; }
    S = S * __expf(M - nm) + s * __expf(m - nm);
    M = nm;
}

__device__ __forceinline__ uint32_t pack_bf16(float a, float b) {
    __nv_bfloat16 ba = __float2bfloat16(a), bb = __float2bfloat16(b);
    return (uint32_t)reinterpret_cast<unsigned short&>(ba) |
           ((uint32_t)reinterpret_cast<unsigned short&>(bb) << 16);
}

// ------------------------- fused prologue: u1 + init + converts -------------------
// CTAs 0..255: U1 = E @ W1e^T + b1 (64x64 tiles, coalesced smem loads).
// CTAs 256..263: zero counters + h replicas.
// CTAs 264..2047: fp32->bf16 conversion of Wg and Ws (grid-strided).
__global__ void __launch_bounds__(256) prep_kernel(const float* __restrict__ X,
                                                   const float* __restrict__ W1,
                                                   const float* __restrict__ b1,
                                                   const int* __restrict__ idx,
                                                   const float* __restrict__ Wg,
                                                   const float* __restrict__ Ws) {
    int c = blockIdx.x;
    int tid = threadIdx.x;

    if (c < 256) {
        // ---------------- u1 tile (coalesced loads) ----------------
        __shared__ float sA[20][64];
        __shared__ float sB[20][64];
        __shared__ int sidx[64];
        int i0 = (c & 15) * 64, t0 = (c >> 4) * 64;
        if (tid < 64) sidx[tid] = idx[t0 + tid];
        __syncthreads();
        float acc[4][4];
#pragma unroll
        for (int a = 0; a < 4; ++a)
#pragma unroll
            for (int b = 0; b < 4; ++b) acc[a][b] = 0.f;
        int tx = tid & 15, ty = tid >> 4;
        for (int kc = 0; kc < 15; ++kc) {
            int k0 = kc * 20;
            for (int i = tid; i < 1280; i += 256) {
                int m = i / 20, k = i - m * 20;    // consecutive threads -> consecutive k
                sA[k][m] = X[(long)sidx[m] * DIM + k0 + k];
                sB[k][m] = W1[(long)(i0 + m) * (DIM + HD1) + k0 + k];
            }
            __syncthreads();
#pragma unroll
            for (int k = 0; k < 20; ++k) {
                float a[4], b[4];
#pragma unroll
                for (int e = 0; e < 4; ++e) { a[e] = sA[k][ty * 4 + e]; b[e] = sB[k][tx * 4 + e]; }
#pragma unroll
                for (int ii = 0; ii < 4; ++ii)
#pragma unroll
                    for (int jj = 0; jj < 4; ++jj) acc[ii][jj] += a[ii] * b[jj];
            }
            __syncthreads();
        }
#pragma unroll
        for (int ii = 0; ii < 4; ++ii)
#pragma unroll
            for (int jj = 0; jj < 4; ++jj) {
                int t = t0 + ty * 4 + ii, n = i0 + tx * 4 + jj;
                g_U1[t * HD1 + n] = acc[ii][jj] + b1[n];
            }
    } else if (c < 264) {
        // ---------------- init ----------------
        int g = (c - 256) * 256 + tid;   // 0..2047
        if (g < 8 * 32) { g_cnt1[g] = 0u; g_cnt2[g] = 0u; }
        if (g < 32) g_tileCtr[g] = 0u;
        for (int i = g; i < 8 * 4 * HD1; i += 2048) ((float*)g_h1rep)[i] = 0.f;
        for (int i = g; i < 8 * 2 * HD2; i += 2048) ((float*)g_h2rep)[i] = 0.f;
    } else {
        // ---------------- converts (Wg then Ws, combined range) ----------------
        const int NW = (2048 - 264) * 256;
        int g = (c - 264) * 256 + tid;
        uint32_t* dG = (uint32_t*)g_Wgb;
        uint32_t* dS = (uint32_t*)g_Wsb;
        const float4* sG = (const float4*)Wg;
        const float4* sS = (const float4*)Ws;
        for (long i = g; i < NG4 + NS4; i += NW) {
            if (i < NG4) {
                float4 v = sG[i];
                dG[2 * i]     = pack_bf16(v.x, v.y);
                dG[2 * i + 1] = pack_bf16(v.z, v.w);
            } else {
                long j = i - NG4;
                float4 v = sS[j];
                dS[2 * j]     = pack_bf16(v.x, v.y);
                dS[2 * j + 1] = pack_bf16(v.z, v.w);
            }
        }
    }
}

// ------------------------- logits tile worker (256 threads, named barrier) ------------
__device__ __noinline__ void tile_worker(char* grp, int ltid, int barid, int cpy,
                                         const float* bg, const float* bs,
                                         float* outG, float* outS, int* sTT) {
    uint16_t* sA = (uint16_t*)grp;                   // [2][128*40]
    uint16_t* sB = (uint16_t*)(grp + 20480);         // [2][128*40]
    float* sBias = (float*)(grp + 40960);            // [128]
    float* sM    = (float*)(grp + 41472);            // [128*2]
    float* sS_   = (float*)(grp + 42496);            // [128*2]
    int lane = ltid & 31;
    int lwarp = ltid >> 5;
    int wm = lwarp & 3, wn = lwarp >> 2;

    for (;;) {
        if (ltid == 0) *sTT = (int)atomicAdd(&g_tileCtr[0], 1u);
        bar_sync(barid);
        int tt = *sTT;
        bar_sync(barid);
        if (tt >= NTILES) break;

        int mblk = tt / TPB, rem = tt % TPB;
        bool isS = rem >= TILES_G;
        int ntile = isS ? rem - TILES_G : rem;
        const uint16_t* Wb = isS ? g_Wsb : g_Wgb;
        const float* bias = isS ? bs : bg;
        float* out = isS ? outS : outG;
        float* pmax = isS ? g_pmaxS : g_pmaxG;
        float* psum = isS ? g_psumS : g_psumG;
        const int V = isS ? VSENS : VGLOB;
        const int pstr = isS ? PSTR_S : PSTR_G;
        int m0 = mblk * 128, n0 = ntile * 128;

        if (ltid == 0) {             // gate: h2s rows <= m0+127 published
            unsigned tgt = (unsigned)(m0 + 128) * NR;
            while (ld_acquire(&g_cnt2[cpy * 32]) < tgt) {}
        }
        if (ltid < 128) {
            int v = n0 + ltid;
            sBias[ltid] = (v < V) ? bias[v] : 0.f;
        }
        bar_sync(barid);

        float acc[2][8][4];
#pragma unroll
        for (int mt = 0; mt < 2; ++mt)
#pragma unroll
            for (int nt = 0; nt < 8; ++nt)
#pragma unroll
                for (int e = 0; e < 4; ++e) acc[mt][nt][e] = 0.f;

        auto issue = [&](int kc, int s) {
            int k0 = kc * 32;
#pragma unroll
            for (int p = 0; p < 2; ++p) {
                int f = ltid + p * 256;
                int row = f >> 2, seg = f & 3;
                cp_async16(&sA[s * 5120 + row * 40 + seg * 8],
                           &g_h2sb[(long)(m0 + row) * HD2 + k0 + seg * 8], 16);
                int vr = n0 + row;
                int srow = vr < V ? vr : 0;
                cp_async16(&sB[s * 5120 + row * 40 + seg * 8],
                           &Wb[(long)srow * HD2 + k0 + seg * 8], vr < V ? 16 : 0);
            }
            cp_commit();
        };

        issue(0, 0);
        for (int kc = 0; kc < 16; ++kc) {
            if (kc + 1 < 16) { issue(kc + 1, (kc + 1) & 1); cp_wait<1>(); }
            else             { cp_wait<0>(); }
            bar_sync(barid);
            const uint16_t* pA = sA + (kc & 1) * 5120;
            const uint16_t* pB = sB + (kc & 1) * 5120;
#pragma unroll
            for (int ks = 0; ks < 2; ++ks) {
                int kk = ks * 16;
                uint32_t a[2][4], b[8][2];
                int ar = wm * 32 + (lane >> 2);
                int ac = kk + (lane & 3) * 2;
#pragma unroll
                for (int mt = 0; mt < 2; ++mt) {
                    const uint16_t* base = &pA[(ar + mt * 16) * 40 + ac];
                    a[mt][0] = *(const uint32_t*)(base);
                    a[mt][1] = *(const uint32_t*)(base + 8 * 40);
                    a[mt][2] = *(const uint32_t*)(base + 8);
                    a[mt][3] = *(const uint32_t*)(base + 8 * 40 + 8);
                }
                int br = wn * 64 + (lane >> 2);
#pragma unroll
                for (int nt = 0; nt < 8; ++nt) {
                    const uint16_t* base = &pB[(br + nt * 8) * 40 + ac];
                    b[nt][0] = *(const uint32_t*)(base);
                    b[nt][1] = *(const uint32_t*)(base + 8);
                }
#pragma unroll
                for (int mt = 0; mt < 2; ++mt)
#pragma unroll
                    for (int nt = 0; nt < 8; ++nt) mma_bf16(acc[mt][nt], a[mt], b[nt]);
            }
            bar_sync(barid);
        }

        int rbase = wm * 32 + (lane >> 2);
        int cbase = wn * 64 + (lane & 3) * 2;
#pragma unroll
        for (int mt = 0; mt < 2; ++mt)
#pragma unroll
            for (int h = 0; h < 2; ++h) {
                int rr = rbase + mt * 16 + h * 8;
                long t = m0 + rr;
                float xs[16];
                float M = -CUDART_INF_F;
#pragma unroll
                for (int nt = 0; nt < 8; ++nt)
#pragma unroll
                    for (int e = 0; e < 2; ++e) {
                        int cc = cbase + nt * 8 + e;
                        int v = n0 + cc;
                        float x = -CUDART_INF_F;
                        if (v < V) {
                            x = acc[mt][nt][h * 2 + e] + sBias[cc];
                            out[t * V + v] = x;
                            M = fmaxf(M, x);
                        }
                        xs[nt * 2 + e] = x;
                    }
                float S = 0.f;
#pragma unroll
                for (int i = 0; i < 16; ++i)
                    if (xs[i] != -CUDART_INF_F) S += __expf(xs[i] - M);
#pragma unroll
                for (int o = 1; o <= 2; o <<= 1) {
                    float m2 = __shfl_xor_sync(~0u, M, o);
                    float s2 = __shfl_xor_sync(~0u, S, o);
                    lse_merge(M, S, m2, s2);
                }
                if ((lane & 3) == 0) { sM[rr * 2 + wn] = M; sS_[rr * 2 + wn] = S; }
            }
        bar_sync(barid);
        if (ltid < 128) {
            float M = sM[ltid * 2], S = sS_[ltid * 2];
            lse_merge(M, S, sM[ltid * 2 + 1], sS_[ltid * 2 + 1]);
            long t = m0 + ltid;
            pmax[t * pstr + ntile] = M;
            psum[t * pstr + ntile] = S;
        }
        bar_sync(barid);
    }
}

// ------------------------- fused RNN + logits kernel (512 threads) -------------------
__global__ void __launch_bounds__(512, 1) fused_kernel(const float* __restrict__ W1,
                                                       const float* __restrict__ W2,
                                                       const float* __restrict__ b2,
                                                       const float* __restrict__ bg,
                                                       const float* __restrict__ bs,
                                                       float* __restrict__ outG,
                                                       float* __restrict__ outS) {
    extern __shared__ __align__(16) char dyn[];
    float* sP1 = (float*)dyn;             // 32 floats
    float* sP2 = (float*)(dyn + 128);     // 16 floats
    int* sTT   = (int*)(dyn + 192);       // [2]
    char* grpA = dyn + 256;
    char* grpB = grpA + GRP_BYTES;

    int tid = threadIdx.x, c = blockIdx.x;
    int lane = tid & 31;
    int cpy = c & 7;

    if (tid < 128) {
        // =================== h1 group (warps 0-3) ===================
        int w = tid >> 5;
        float w1r[8][8];   // [jj][q]
#pragma unroll
        for (int q = 0; q < 8; ++q) {
            const float* p = W1 + (long)(c * 8 + q) * (DIM + HD1) + DIM;
#pragma unroll
            for (int jj = 0; jj < 8; ++jj)
                w1r[jj][q] = p[w * 256 + jj * 32 + lane];
        }

        for (int r = 0; r < T_STEPS; ++r) {
            float u1v = 0.f;
            if (tid < 8) u1v = __ldg(&g_U1[r * HD1 + c * 8 + tid]);
            if (tid == 0) {
                if (r >= 4) {   // WAR gate (usually satisfied), overlapping cnt1 wait
                    unsigned t2 = (unsigned)(r - 3) * NR;
                    while (ld_acquire(&g_cnt2[cpy * 32]) < t2) {}
                }
                if (r > 0) {
                    unsigned t1 = (unsigned)r * NR;
                    while (ld_acquire(&g_cnt1[cpy * 32]) < t1) {}
                }
            }
            asm volatile("bar.sync 1, 128;" ::: "memory");

            const float* h1p = g_h1rep[cpy][(r + 3) & 3];   // h1(r-1)
            float p1[8] = {0, 0, 0, 0, 0, 0, 0, 0};
#pragma unroll
            for (int jj = 0; jj < 8; ++jj) {
                float h = __ldcg(&h1p[w * 256 + jj * 32 + lane]);
#pragma unroll
                for (int q = 0; q < 8; ++q) p1[q] += w1r[jj][q] * h;
            }
#pragma unroll
            for (int q = 0; q < 8; ++q)
#pragma unroll
                for (int o = 16; o; o >>= 1) p1[q] += __shfl_xor_sync(~0u, p1[q], o);
            if (lane == 0) {
#pragma unroll
                for (int q = 0; q < 8; ++q) sP1[q * 4 + w] = p1[q];
            }
            asm volatile("bar.sync 1, 128;" ::: "memory");

            if (w == 0) {
                float s = 0.f;
                if (lane < 8) {
                    float4 ps = *(const float4*)&sP1[lane * 4];
                    s = u1v + ps.x + ps.y + ps.z + ps.w;
                    s = s > 0.f ? s : 0.01f * s;
                }
                float sv[8];
#pragma unroll
                for (int q = 0; q < 8; ++q) sv[q] = __shfl_sync(~0u, s, q);
                if (lane < 8) {
                    float* dst = &g_h1rep[lane][r & 3][c * 8];
                    stcg4(dst,     make_float4(sv[0], sv[1], sv[2], sv[3]));
                    stcg4(dst + 4, make_float4(sv[4], sv[5], sv[6], sv[7]));
                    red_release(&g_cnt1[lane * 32], 1u);
                }
            }
        }
        tile_worker(grpB, tid, 4, cpy, bg, bs, outG, outS, &sTT[1]);
    } else if (tid < 256) {
        // =================== h2 group (warps 4-7) ===================
        int w = (tid >> 5) - 4;
        float w2a[8][4], w2b[4][4];
#pragma unroll
        for (int q = 0; q < 4; ++q) {
            const float* p = W2 + (long)(c * 4 + q) * (HD1 + HD2);
#pragma unroll
            for (int jj = 0; jj < 8; ++jj)
                w2a[jj][q] = p[w * 256 + jj * 32 + lane];
#pragma unroll
            for (int jj = 0; jj < 4; ++jj)
                w2b[jj][q] = p[HD1 + w * 128 + jj * 32 + lane];
        }
        float b2v = 0.f;
        if (tid >= 128 && tid < 132) b2v = b2[c * 4 + (tid - 128)];

        for (int r = 1; r <= T_STEPS; ++r) {
            if (tid == 128) {
                unsigned t1 = (unsigned)r * NR;
                while (ld_acquire(&g_cnt1[cpy * 32]) < t1) {}
                if (r > 1) {
                    unsigned t2 = (unsigned)(r - 1) * NR;
                    while (ld_acquire(&g_cnt2[cpy * 32]) < t2) {}
                }
            }
            asm volatile("bar.sync 2, 128;" ::: "memory");

            const float* h1p = g_h1rep[cpy][(r + 3) & 3];   // h1(r-1)
            const float* h2p = g_h2rep[cpy][r & 1];          // h2(r-2)
            float p2[4] = {0, 0, 0, 0};
#pragma unroll
            for (int jj = 0; jj < 8; ++jj) {
                float h = __ldcg(&h1p[w * 256 + jj * 32 + lane]);
#pragma unroll
                for (int q = 0; q < 4; ++q) p2[q] += w2a[jj][q] * h;
            }
#pragma unroll
            for (int jj = 0; jj < 4; ++jj) {
                float h = __ldcg(&h2p[w * 128 + jj * 32 + lane]);
#pragma unroll
                for (int q = 0; q < 4; ++q) p2[q] += w2b[jj][q] * h;
            }
#pragma unroll
            for (int q = 0; q < 4; ++q)
#pragma unroll
                for (int o = 16; o; o >>= 1) p2[q] += __shfl_xor_sync(~0u, p2[q], o);
            if (lane == 0) {
#pragma unroll
                for (int q = 0; q < 4; ++q) sP2[q * 4 + w] = p2[q];
            }
            asm volatile("bar.sync 2, 128;" ::: "memory");

            if (w == 0) {
                float s = 0.f;
                if (lane < 4) {
                    float4 ps = *(const float4*)&sP2[lane * 4];
                    s = b2v + ps.x + ps.y + ps.z + ps.w;
                    s = s > 0.f ? s : 0.01f * s;
                }
                float sv[4];
#pragma unroll
                for (int q = 0; q < 4; ++q) sv[q] = __shfl_sync(~0u, s, q);
                if (lane < 8) {
                    stcg4(&g_h2rep[lane][(r + 1) & 1][c * 4],
                          make_float4(sv[0], sv[1], sv[2], sv[3]));
                    unsigned long long hv =
                        (unsigned long long)pack_bf16(sv[0], sv[1]) |
                        ((unsigned long long)pack_bf16(sv[2], sv[3]) << 32);
                    *(unsigned long long*)&g_h2sb[(r - 1) * HD2 + c * 4] = hv;
                    red_release(&g_cnt2[lane * 32], 1u);
                }
            }
        }
        tile_worker(grpB, tid, 4, cpy, bg, bs, outG, outS, &sTT[1]);
    } else {
        tile_worker(grpA, tid - 256, 3, cpy, bg, bs, outG, outS, &sTT[0]);
    }
}

// ------------------------- per-row LSE reduction -------------------------
__global__ void lse_kernel() {
    int t = blockIdx.x;
    int which = blockIdx.y;
    const float* pm = which ? g_pmaxS : g_pmaxG;
    const float* ps = which ? g_psumS : g_psumG;
    int nb = which ? TILES_S : TILES_G;
    int pstr = which ? PSTR_S : PSTR_G;
    float M = -CUDART_INF_F, S = 0.f;
    for (int i = threadIdx.x; i < nb; i += 128)
        lse_merge(M, S, pm[(long)t * pstr + i], ps[(long)t * pstr + i]);
#pragma unroll
    for (int o = 16; o; o >>= 1) {
        float m2 = __shfl_xor_sync(~0u, M, o);
        float s2 = __shfl_xor_sync(~0u, S, o);
        lse_merge(M, S, m2, s2);
    }
    __shared__ float sm_[4], ss_[4];
    int w = threadIdx.x >> 5;
    if ((threadIdx.x & 31) == 0) { sm_[w] = M; ss_[w] = S; }
    __syncthreads();
    if (threadIdx.x == 0) {
        for (int k = 1; k < 4; ++k) lse_merge(M, S, sm_[k], ss_[k]);
        float lse = M + logf(S);
        if (which) g_lseS[t] = lse; else g_lseG[t] = lse;
    }
}

// ------------------------- in-place logp = logit - lse (row from blockIdx.y) -------------
__global__ void sub_kernel(float* __restrict__ base, int which, int V) {
    int t = blockIdx.y;
    float l = (which ? g_lseS : g_lseG)[t];
    float4* row = (float4*)(base + (size_t)t * V);
    int n4 = V >> 2;
    for (int i = blockIdx.x * blockDim.x + threadIdx.x; i < n4; i += gridDim.x * blockDim.x) {
        float4 v = row[i];
        v.x -= l; v.y -= l; v.z -= l; v.w -= l;
        row[i] = v;
    }
}

// ------------------------- launcher -------------------------
extern "C" void kernel_launch(void* const* d_in, const int* in_sizes, int n_in,
                              void* d_out, int out_size) {
    const float* X  = (const float*)d_in[0];
    const float* W1 = (const float*)d_in[1];
    const float* b1 = (const float*)d_in[2];
    const float* W2 = (const float*)d_in[3];
    const float* b2 = (const float*)d_in[4];
    const float* Wg = (const float*)d_in[5];
    const float* bg = (const float*)d_in[6];
    const float* Ws = (const float*)d_in[7];
    const float* bs = (const float*)d_in[8];
    const int*  idx = (const int*)d_in[9];
    float* outG = (float*)d_out;
    float* outS = outG + (size_t)T_STEPS * VGLOB;

    cudaFuncSetAttribute(fused_kernel, cudaFuncAttributeMaxDynamicSharedMemorySize, DYN_BYTES);

    prep_kernel<<<2048, 256>>>(X, W1, b1, idx, Wg, Ws);
    fused_kernel<<<NR, 512, DYN_BYTES>>>(W1, W2, b2, bg, bs, outG, outS);
    lse_kernel<<<dim3(T_STEPS, 2), 128>>>();
    sub_kernel<<<dim3(49, T_STEPS), 256>>>(outG, 0, VGLOB);
    sub_kernel<<<dim3(25, T_STEPS), 256>>>(outS, 1, VSENS);
}